// round 16
// baseline (speedup 1.0000x reference)
#include <cuda_runtime.h>
#include <cstdint>
#include <math.h>

#define N_IN   8192
#define N_MC   32768
#define K_TOP  656
#define MASK_WORDS (N_IN / 32)          // 256
#define NBLK   148                      // persistent: one block per SM
#define ROWS_PER_TICKET 2
#define TICKETS (N_MC / ROWS_PER_TICKET)
#define NWARPS  (NBLK * 32)
#define SLICE_BLOCKS 128                // tail: 128 blocks x 256 keys
#define SLICE  256

__device__ float    g_overlap[N_MC];
__device__ uint32_t g_hist16[65536];    // top-16-bit hist, 64 rows x 1024
__device__ uint32_t g_rcnt16[64];       // row counts (top 6 bits)
__device__ uint32_t g_hist2[65536];     // low-16-bit hist of candidates
__device__ uint32_t g_rcnt2[64];
__device__ uint32_t g_tie[SLICE_BLOCKS];
__device__ uint32_t g_row;              // stream refill ticket
__device__ uint32_t g_arrive, g_exit, g_rel;   // barrier state (reset by last exiter)

__device__ __forceinline__ uint32_t warp_incl_scan(uint32_t v) {
    #pragma unroll
    for (int off = 1; off < 32; off <<= 1) {
        uint32_t u = __shfl_up_sync(0xffffffffu, v, off);
        if ((threadIdx.x & 31) >= off) v += u;
    }
    return v;
}

// reset-safe spin grid barrier: stage s completes when g_arrive hits s*NBLK
__device__ __forceinline__ void grid_barrier(int stage) {
    __syncthreads();
    __threadfence();
    if (threadIdx.x == 0) {
        uint32_t a = atomicAdd(&g_arrive, 1u);
        if (a == (uint32_t)(stage * NBLK - 1)) {
            atomicExch(&g_rel, (uint32_t)stage);
        } else {
            while (atomicAdd(&g_rel, 0u) < (uint32_t)stage)
                __nanosleep(64);
        }
    }
    __syncthreads();
    __threadfence();
}

// 2-level exact select over a 64x1024 hist (block-cooperative, 1024 thr)
struct SelScratch {
    uint32_t rowcp[1024];
    uint32_t gs[32];
    uint32_t bin;
    int      rem;
    int      rowpick;
    int      need;
};

__device__ void select_stage(const uint32_t* __restrict__ cnt64,
                             const uint32_t* __restrict__ hist,
                             int need_in, SelScratch* s)
{
    const int tid = threadIdx.x, wid = tid >> 5, lane = tid & 31;
    if (wid == 0) {
        uint32_t d0 = cnt64[63 - lane];            // descending pos 0..31
        uint32_t d1 = cnt64[31 - lane];            // pos 32..63
        uint32_t i0 = warp_incl_scan(d0);
        uint32_t tot0 = __shfl_sync(0xffffffffu, i0, 31);
        uint32_t i1 = warp_incl_scan(d1) + tot0;
        uint32_t e0 = i0 - d0, e1 = i1 - d1;
        if ((int)e0 < need_in && (int)i0 >= need_in) { s->rowpick = 63 - lane; s->need = need_in - (int)e0; }
        if ((int)e1 < need_in && (int)i1 >= need_in) { s->rowpick = 31 - lane; s->need = need_in - (int)e1; }
    }
    __syncthreads();
    const int rp = s->rowpick;
    s->rowcp[tid] = hist[rp * 1024 + tid];
    __syncthreads();
    {
        uint32_t v = s->rowcp[wid * 32 + lane];
        v = __reduce_add_sync(0xffffffffu, v);
        if (lane == 0) s->gs[wid] = v;
    }
    __syncthreads();
    if (wid == 0) {
        uint32_t dg = s->gs[31 - lane];
        uint32_t ginc = warp_incl_scan(dg);
        uint32_t gexcl = ginc - dg;
        int need = s->need;
        bool gc = ((int)gexcl < need && (int)ginc >= need);
        unsigned gb = __ballot_sync(0xffffffffu, gc);
        int glane = __ffs(gb) - 1;
        int gstar = 31 - glane;
        int need2 = need - (int)__shfl_sync(0xffffffffu, gexcl, glane);
        uint32_t h = s->rowcp[gstar * 32 + (31 - lane)];
        uint32_t inc = warp_incl_scan(h);
        bool cc = ((int)(inc - h) < need2 && (int)inc >= need2);
        if (cc) {                                  // exactly one lane
            s->bin = (uint32_t)(rp * 1024 + gstar * 32 + (31 - lane));
            s->rem = need2 - (int)(inc - h);
        }
    }
    __syncthreads();
}

// ---------------------------------------------------------------------------
// Persistent fused kernel (148 blocks x 1024 threads, 1 block/SM declared):
//  stream: per-warp 2-row tickets; EXPLICIT 8-wide float4 batches keep 32
//          data regs live -> ptxas cannot collapse the MLP (R15 lesson)
//  tail (grid-parallel, 3 spin barriers): exact top-K via two 2-level hist
//  selects + distributed tie-ranked marking (lowest-index-first ties).
// ---------------------------------------------------------------------------
__global__ __launch_bounds__(1024, 1) void spatial_pooler_kernel(
    const float* __restrict__ I,
    const float* __restrict__ perm,
    const float* __restrict__ duty,
    const float* __restrict__ navg,
    float* __restrict__ out)
{
    __shared__ uint32_t  smask[MASK_WORDS];
    __shared__ SelScratch ss;
    __shared__ uint32_t  s_T16; __shared__ int s_r16;
    __shared__ uint32_t  s_T;   __shared__ int s_r;
    __shared__ uint32_t  s_wt[8];
    __shared__ uint32_t  s_tp;

    const int tid  = threadIdx.x;
    const int wid  = tid >> 5;
    const int lane = tid & 31;

    // ---------------- mask build (once per block) ----------------
    #pragma unroll
    for (int k2 = 0; k2 < 8; ++k2) {
        float v = I[k2 * 1024 + tid];
        unsigned ball = __ballot_sync(0xffffffffu, v != 0.0f);
        if (lane == 0) smask[k2 * 32 + wid] = ball;
    }
    __syncthreads();

    // ---------------- streaming loop: per-warp 2-row tickets ----------------
    {
        uint32_t t = (uint32_t)(blockIdx.x * 32 + wid);   // static first ticket
        while (t < TICKETS) {
            uint32_t nt = 0xffffffffu;
            if (lane == 0) nt = NWARPS + atomicAdd(&g_row, 1u);  // prefetch

            #pragma unroll
            for (int rr = 0; rr < ROWS_PER_TICKET; ++rr) {
                const int row = (int)t * ROWS_PER_TICKET + rr;
                const float4* p =
                    reinterpret_cast<const float4*>(perm + (size_t)row * N_IN);

                int cnt = 0;
                #pragma unroll
                for (int it = 0; it < 8; ++it) {
                    // 8 loads in flight BEFORE any consumption: forces
                    // 32 live data regs -> MLP-8 survives reg allocation
                    float4 v[8];
                    #pragma unroll
                    for (int j = 0; j < 8; ++j)
                        v[j] = __ldcs(&p[it * 256 + j * 32 + lane]);
                    #pragma unroll
                    for (int j = 0; j < 8; ++j) {
                        int c = (it * 256 + j * 32 + lane) * 4;
                        uint32_t m = smask[c >> 5] >> (c & 31);
                        cnt += ((m & 1u) && v[j].x >= 0.5f);
                        cnt += ((m & 2u) && v[j].y >= 0.5f);
                        cnt += ((m & 4u) && v[j].z >= 0.5f);
                        cnt += ((m & 8u) && v[j].w >= 0.5f);
                    }
                }
                cnt = __reduce_add_sync(0xffffffffu, cnt);

                if (lane == 0) {
                    float d = navg[row] - duty[row];
                    float boost = (float)exp((double)d);  // exact f32 exp
                    float val = boost * (float)cnt;
                    uint32_t bits = __float_as_uint(val);
                    g_overlap[row] = val;
                    atomicAdd(&g_hist16[bits >> 16], 1u);
                    atomicAdd(&g_rcnt16[bits >> 26], 1u);
                }
            }
            t = __shfl_sync(0xffffffffu, nt, 0);
        }
    }

    // =================== grid-parallel exact top-K tail ===================
    grid_barrier(1);                     // all rows + hist REDs visible

    const int  blk    = blockIdx.x;
    const bool slicer = (blk < SLICE_BLOCKS);
    uint32_t myk = 0;
    int      myj = 0;

    if (slicer) {
        // phase 1 (redundant per block): top-16 threshold bin
        select_stage(g_rcnt16, g_hist16, K_TOP, &ss);
        if (tid == 0) { s_T16 = ss.bin << 16; s_r16 = ss.rem; }
        __syncthreads();

        // phase 2: candidates' low-16 bits into second 2-level hist
        if (tid < SLICE) {
            myj = blk * SLICE + tid;
            myk = __float_as_uint(g_overlap[myj]);
            if ((myk & 0xFFFF0000u) == s_T16) {
                atomicAdd(&g_hist2[myk & 0xFFFFu], 1u);
                atomicAdd(&g_rcnt2[(myk >> 10) & 63u], 1u);
            }
        }
    }
    grid_barrier(2);                     // candidate hist complete

    if (slicer) {
        // phase 3 (redundant): exact 32-bit threshold T + tie budget r
        select_stage(g_rcnt2, g_hist2, s_r16, &ss);
        if (tid == 0) { s_T = s_T16 | ss.bin; s_r = ss.rem; }
        __syncthreads();

        // phase 4: per-block tie count (tid order == index order)
        if (tid < SLICE) {
            unsigned ball = __ballot_sync(0xffffffffu, myk == s_T);
            if (lane == 0) s_wt[wid] = (uint32_t)__popc(ball);
        }
        __syncthreads();
        if (tid == 0) {
            uint32_t tot = 0;
            #pragma unroll
            for (int w = 0; w < 8; ++w) tot += s_wt[w];
            g_tie[blk] = tot;
        }
    }
    grid_barrier(3);                     // all tie counts visible

    if (slicer) {
        // phase 5a: global tie prefix = sum of g_tie over blocks before mine
        if (wid == 0) {
            uint32_t v = 0;
            #pragma unroll
            for (int q = 0; q < 4; ++q) {
                int idx = q * 32 + lane;
                v += (idx < blk) ? g_tie[idx] : 0u;
            }
            v = __reduce_add_sync(0xffffffffu, v);
            if (lane == 0) s_tp = v;
        }
        __syncthreads();

        // phase 5b: rank ties (lowest index first) and mark
        if (tid < SLICE) {
            unsigned ball = __ballot_sync(0xffffffffu, myk == s_T);
            int lanepre = __popc(ball & ((1u << lane) - 1u));
            int wpre = 0;
            #pragma unroll
            for (int w = 0; w < 8; ++w) wpre += (w < wid) ? (int)s_wt[w] : 0;
            int grank = (int)s_tp + wpre + lanepre;
            uint32_t T = s_T;
            out[myj] = ((myk > T) || (myk == T && grank < s_r)) ? 1.0f : 0.0f;
        }

        // phase 5c: zero hists for next launch (all reads completed pre-B3)
        if (tid < 512) {
            int base = blk * 512 + tid;
            g_hist16[base] = 0u;
            g_hist2[base]  = 0u;
        }
        if (blk == 0 && tid < 64) g_rcnt16[tid] = 0u;
        if (blk == 1 && tid < 64) g_rcnt2[tid]  = 0u;
    }

    // ---------------- exit: last block resets barrier/ticket state ----------
    __syncthreads();
    __threadfence();
    if (tid == 0) {
        uint32_t e = atomicAdd(&g_exit, 1u);
        if (e == NBLK - 1) {             // provably last user of all state
            g_row = 0u;
            g_arrive = 0u;
            g_rel = 0u;
            g_exit = 0u;
        }
    }
}

// ---------------------------------------------------------------------------
extern "C" void kernel_launch(void* const* d_in, const int* in_sizes, int n_in,
                              void* d_out, int out_size)
{
    const float* I    = (const float*)d_in[0];
    const float* perm = (const float*)d_in[1];
    const float* duty = (const float*)d_in[2];
    const float* navg = (const float*)d_in[3];
    float* out = (float*)d_out;

    (void)in_sizes; (void)n_in; (void)out_size;

    spatial_pooler_kernel<<<NBLK, 1024>>>(I, perm, duty, navg, out);
}

// round 17
// speedup vs baseline: 1.7045x; 1.7045x over previous
#include <cuda_runtime.h>
#include <cstdint>
#include <math.h>

#define N_IN   8192
#define N_MC   32768
#define K_TOP  656
#define MASK_WORDS (N_IN / 32)          // 256
#define NBLK   148                      // persistent: one block per SM
#define ROWS_PER_TICKET 2
#define TICKETS (N_MC / ROWS_PER_TICKET)
#define NWARPS  (NBLK * 32)
#define SLICE_BLOCKS 128                // tail: 128 blocks x 256 keys
#define SLICE  256

__device__ float    g_overlap[N_MC];
__device__ uint32_t g_hist16[65536];    // top-16-bit hist, 64 rows x 1024
__device__ uint32_t g_rcnt16[64];       // row counts (top 6 bits)
__device__ uint32_t g_hist2[65536];     // low-16-bit hist of candidates
__device__ uint32_t g_rcnt2[64];
__device__ uint32_t g_tie[SLICE_BLOCKS];
__device__ uint32_t g_row;              // stream refill ticket
__device__ uint32_t g_arrive, g_exit, g_rel;   // barrier state (reset by last exiter)

__device__ __forceinline__ uint32_t warp_incl_scan(uint32_t v) {
    #pragma unroll
    for (int off = 1; off < 32; off <<= 1) {
        uint32_t u = __shfl_up_sync(0xffffffffu, v, off);
        if ((threadIdx.x & 31) >= off) v += u;
    }
    return v;
}

// reset-safe spin grid barrier: stage s completes when g_arrive hits s*NBLK
__device__ __forceinline__ void grid_barrier(int stage) {
    __syncthreads();
    __threadfence();
    if (threadIdx.x == 0) {
        uint32_t a = atomicAdd(&g_arrive, 1u);
        if (a == (uint32_t)(stage * NBLK - 1)) {
            atomicExch(&g_rel, (uint32_t)stage);
        } else {
            while (atomicAdd(&g_rel, 0u) < (uint32_t)stage)
                __nanosleep(64);
        }
    }
    __syncthreads();
    __threadfence();
}

// 2-level exact select over a 64x1024 hist (block-cooperative, 1024 thr)
struct SelScratch {
    uint32_t rowcp[1024];
    uint32_t gs[32];
    uint32_t bin;
    int      rem;
    int      rowpick;
    int      need;
};

__device__ void select_stage(const uint32_t* __restrict__ cnt64,
                             const uint32_t* __restrict__ hist,
                             int need_in, SelScratch* s)
{
    const int tid = threadIdx.x, wid = tid >> 5, lane = tid & 31;
    if (wid == 0) {
        uint32_t d0 = cnt64[63 - lane];            // descending pos 0..31
        uint32_t d1 = cnt64[31 - lane];            // pos 32..63
        uint32_t i0 = warp_incl_scan(d0);
        uint32_t tot0 = __shfl_sync(0xffffffffu, i0, 31);
        uint32_t i1 = warp_incl_scan(d1) + tot0;
        uint32_t e0 = i0 - d0, e1 = i1 - d1;
        if ((int)e0 < need_in && (int)i0 >= need_in) { s->rowpick = 63 - lane; s->need = need_in - (int)e0; }
        if ((int)e1 < need_in && (int)i1 >= need_in) { s->rowpick = 31 - lane; s->need = need_in - (int)e1; }
    }
    __syncthreads();
    const int rp = s->rowpick;
    s->rowcp[tid] = hist[rp * 1024 + tid];
    __syncthreads();
    {
        uint32_t v = s->rowcp[wid * 32 + lane];
        v = __reduce_add_sync(0xffffffffu, v);
        if (lane == 0) s->gs[wid] = v;
    }
    __syncthreads();
    if (wid == 0) {
        uint32_t dg = s->gs[31 - lane];
        uint32_t ginc = warp_incl_scan(dg);
        uint32_t gexcl = ginc - dg;
        int need = s->need;
        bool gc = ((int)gexcl < need && (int)ginc >= need);
        unsigned gb = __ballot_sync(0xffffffffu, gc);
        int glane = __ffs(gb) - 1;
        int gstar = 31 - glane;
        int need2 = need - (int)__shfl_sync(0xffffffffu, gexcl, glane);
        uint32_t h = s->rowcp[gstar * 32 + (31 - lane)];
        uint32_t inc = warp_incl_scan(h);
        bool cc = ((int)(inc - h) < need2 && (int)inc >= need2);
        if (cc) {                                  // exactly one lane
            s->bin = (uint32_t)(rp * 1024 + gstar * 32 + (31 - lane));
            s->rem = need2 - (int)(inc - h);
        }
    }
    __syncthreads();
}

// ---------------------------------------------------------------------------
// Persistent fused kernel (148 blocks x 1024 threads, 1 block/SM declared so
// ptxas schedules for the 64-reg budget -> R14's spill-free MLP-8 stream):
//  stream: per-warp 2-row tickets; R14 loop form (#pragma unroll 8)
//  tail (grid-parallel, 3 spin barriers): exact top-K via two 2-level hist
//  selects + distributed tie-ranked marking (lowest-index-first ties).
// ---------------------------------------------------------------------------
__global__ __launch_bounds__(1024, 1) void spatial_pooler_kernel(
    const float* __restrict__ I,
    const float* __restrict__ perm,
    const float* __restrict__ duty,
    const float* __restrict__ navg,
    float* __restrict__ out)
{
    __shared__ uint32_t  smask[MASK_WORDS];
    __shared__ SelScratch ss;
    __shared__ uint32_t  s_T16; __shared__ int s_r16;
    __shared__ uint32_t  s_T;   __shared__ int s_r;
    __shared__ uint32_t  s_wt[8];
    __shared__ uint32_t  s_tp;

    const int tid  = threadIdx.x;
    const int wid  = tid >> 5;
    const int lane = tid & 31;

    // ---------------- mask build (once per block) ----------------
    #pragma unroll
    for (int k2 = 0; k2 < 8; ++k2) {
        float v = I[k2 * 1024 + tid];
        unsigned ball = __ballot_sync(0xffffffffu, v != 0.0f);
        if (lane == 0) smask[k2 * 32 + wid] = ball;
    }
    __syncthreads();

    // ---------------- streaming loop: per-warp 2-row tickets ----------------
    // R14's exact loop form: ptxas batches 8 float4 loads under the 64-reg
    // budget without spilling (verified R14: 64 regs, 5.8 TB/s).
    {
        uint32_t t = (uint32_t)(blockIdx.x * 32 + wid);   // static first ticket
        while (t < TICKETS) {
            uint32_t nt = 0xffffffffu;
            if (lane == 0) nt = NWARPS + atomicAdd(&g_row, 1u);  // prefetch

            #pragma unroll
            for (int rr = 0; rr < ROWS_PER_TICKET; ++rr) {
                const int row = (int)t * ROWS_PER_TICKET + rr;
                const float4* p =
                    reinterpret_cast<const float4*>(perm + (size_t)row * N_IN);

                int cnt = 0;
                #pragma unroll 8
                for (int it = 0; it < 64; ++it) {
                    int c4 = it * 32 + lane;
                    float4 v = __ldcs(&p[c4]);       // streaming, evict-first
                    int c = c4 * 4;
                    uint32_t m = smask[c >> 5] >> (c & 31);
                    cnt += ((m & 1u) && v.x >= 0.5f);
                    cnt += ((m & 2u) && v.y >= 0.5f);
                    cnt += ((m & 4u) && v.z >= 0.5f);
                    cnt += ((m & 8u) && v.w >= 0.5f);
                }
                cnt = __reduce_add_sync(0xffffffffu, cnt);

                if (lane == 0) {
                    float d = navg[row] - duty[row];
                    float boost = (float)exp((double)d);  // exact f32 exp
                    float val = boost * (float)cnt;
                    uint32_t bits = __float_as_uint(val);
                    g_overlap[row] = val;
                    atomicAdd(&g_hist16[bits >> 16], 1u);
                    atomicAdd(&g_rcnt16[bits >> 26], 1u);
                }
            }
            t = __shfl_sync(0xffffffffu, nt, 0);
        }
    }

    // =================== grid-parallel exact top-K tail ===================
    grid_barrier(1);                     // all rows + hist REDs visible

    const int  blk    = blockIdx.x;
    const bool slicer = (blk < SLICE_BLOCKS);
    uint32_t myk = 0;
    int      myj = 0;

    if (slicer) {
        // phase 1 (redundant per block): top-16 threshold bin
        select_stage(g_rcnt16, g_hist16, K_TOP, &ss);
        if (tid == 0) { s_T16 = ss.bin << 16; s_r16 = ss.rem; }
        __syncthreads();

        // phase 2: candidates' low-16 bits into second 2-level hist
        if (tid < SLICE) {
            myj = blk * SLICE + tid;
            myk = __float_as_uint(g_overlap[myj]);
            if ((myk & 0xFFFF0000u) == s_T16) {
                atomicAdd(&g_hist2[myk & 0xFFFFu], 1u);
                atomicAdd(&g_rcnt2[(myk >> 10) & 63u], 1u);
            }
        }
    }
    grid_barrier(2);                     // candidate hist complete

    if (slicer) {
        // phase 3 (redundant): exact 32-bit threshold T + tie budget r
        select_stage(g_rcnt2, g_hist2, s_r16, &ss);
        if (tid == 0) { s_T = s_T16 | ss.bin; s_r = ss.rem; }
        __syncthreads();

        // phase 4: per-block tie count (tid order == index order)
        if (tid < SLICE) {
            unsigned ball = __ballot_sync(0xffffffffu, myk == s_T);
            if (lane == 0) s_wt[wid] = (uint32_t)__popc(ball);
        }
        __syncthreads();
        if (tid == 0) {
            uint32_t tot = 0;
            #pragma unroll
            for (int w = 0; w < 8; ++w) tot += s_wt[w];
            g_tie[blk] = tot;
        }
    }
    grid_barrier(3);                     // all tie counts visible

    if (slicer) {
        // phase 5a: global tie prefix = sum of g_tie over blocks before mine
        if (wid == 0) {
            uint32_t v = 0;
            #pragma unroll
            for (int q = 0; q < 4; ++q) {
                int idx = q * 32 + lane;
                v += (idx < blk) ? g_tie[idx] : 0u;
            }
            v = __reduce_add_sync(0xffffffffu, v);
            if (lane == 0) s_tp = v;
        }
        __syncthreads();

        // phase 5b: rank ties (lowest index first) and mark
        if (tid < SLICE) {
            unsigned ball = __ballot_sync(0xffffffffu, myk == s_T);
            int lanepre = __popc(ball & ((1u << lane) - 1u));
            int wpre = 0;
            #pragma unroll
            for (int w = 0; w < 8; ++w) wpre += (w < wid) ? (int)s_wt[w] : 0;
            int grank = (int)s_tp + wpre + lanepre;
            uint32_t T = s_T;
            out[myj] = ((myk > T) || (myk == T && grank < s_r)) ? 1.0f : 0.0f;
        }

        // phase 5c: zero hists for next launch (all reads completed pre-B3)
        if (tid < 512) {
            int base = blk * 512 + tid;
            g_hist16[base] = 0u;
            g_hist2[base]  = 0u;
        }
        if (blk == 0 && tid < 64) g_rcnt16[tid] = 0u;
        if (blk == 1 && tid < 64) g_rcnt2[tid]  = 0u;
    }

    // ---------------- exit: last block resets barrier/ticket state ----------
    __syncthreads();
    __threadfence();
    if (tid == 0) {
        uint32_t e = atomicAdd(&g_exit, 1u);
        if (e == NBLK - 1) {             // provably last user of all state
            g_row = 0u;
            g_arrive = 0u;
            g_rel = 0u;
            g_exit = 0u;
        }
    }
}

// ---------------------------------------------------------------------------
extern "C" void kernel_launch(void* const* d_in, const int* in_sizes, int n_in,
                              void* d_out, int out_size)
{
    const float* I    = (const float*)d_in[0];
    const float* perm = (const float*)d_in[1];
    const float* duty = (const float*)d_in[2];
    const float* navg = (const float*)d_in[3];
    float* out = (float*)d_out;

    (void)in_sizes; (void)n_in; (void)out_size;

    spatial_pooler_kernel<<<NBLK, 1024>>>(I, perm, duty, navg, out);
}